// round 5
// baseline (speedup 1.0000x reference)
#include <cuda_runtime.h>
#include <cuda_bf16.h>
#include <math.h>
#include <stdint.h>

// ===================== problem constants =====================
#define NB   16
#define NC   256
#define NHW  1024
#define NTOK (NB * NHW)        // 16384
#define NK   8192
#define NQ   (NB * NC * NHW)   // 4194304

#define DELTA 16.0f
#define CAND_CAP 16
#define CK_STRIDE 64

// ===================== device scratch =====================
__device__ __align__(16) uint32_t g_zfrag[(NTOK / 128) * 8192];   // 4MB, fp8 frag-order A
__device__ __align__(16) uint16_t g_ef8[NK * NC / 2];             // 2MB, e4m3(-2e) pairs
__device__ float  g_cbnorm[NK];
__device__ __align__(16) int g_idx[NTOK];
__device__ int    g_nc[NTOK];
__device__ int    g_ck[NTOK * CK_STRIDE];
__device__ int    g_counts[NK];
__device__ double g_loss;

__device__ __forceinline__ uint32_t smem_u32(const void* p) {
    uint32_t a;
    asm("{ .reg .u64 t; cvta.to.shared.u64 t, %1; cvt.u32.u64 %0, t; }" : "=r"(a) : "l"(p));
    return a;
}
// pack two f32 -> e4m3x2 (hi in upper byte)
__device__ __forceinline__ uint16_t f2_to_e4m3x2(float hi, float lo) {
    uint16_t v;
    asm("cvt.rn.satfinite.e4m3x2.f32 %0, %1, %2;" : "=h"(v) : "f"(hi), "f"(lo));
    return v;
}

// ===================== init =====================
__global__ void vq_init_kernel() {
    int id = blockIdx.x * blockDim.x + threadIdx.x;
    if (id < NK) g_counts[id] = 0;
    if (id == 0) g_loss = 0.0;
}

// ===================== prep z: transpose + e4m3 + m16n8k32 fragment order ============
// token n: m=n&127, blk=n>>7. Frag u32 at (((blk*8+ks)*8+mt)*32+lane)*4+r holds 4 fp8
// (k ascending bytes), where k-chunk ks (32 wide), rh=bit4 of k, tg=(k>>2)&3,
// lane = g*4+tg (g = row&7), r = rl + 2*rh (rl = row-half).
__global__ void vq_prep_z_kernel(const float* __restrict__ z) {
    __shared__ float t[32][33];
    int b   = blockIdx.z;
    int hw0 = blockIdx.x * 32;
    int c0  = blockIdx.y * 32;
    int lane = threadIdx.x & 31;
    int gq   = threadIdx.x >> 5;   // 0..7
    const float* zp = z + ((size_t)b * NC + c0) * NHW + hw0;
#pragma unroll
    for (int r = 0; r < 4; r++) {
        int cc = gq * 4 + r;
        t[cc][lane] = zp[(size_t)cc * NHW + lane];
    }
    __syncthreads();
    {
        int hw_i = threadIdx.x & 31;
        int cp   = threadIdx.x >> 5;            // 0..7 -> 4 channels each
        int cl   = 4 * cp;
        float v0 = t[cl][hw_i], v1 = t[cl + 1][hw_i];
        float v2 = t[cl + 2][hw_i], v3 = t[cl + 3][hw_i];
        uint32_t p01 = f2_to_e4m3x2(v1, v0);
        uint32_t p23 = f2_to_e4m3x2(v3, v2);
        uint32_t pk = p01 | (p23 << 16);

        int n   = b * NHW + hw0 + hw_i;
        int m   = n & 127;
        int blk = n >> 7;
        int k   = c0 + cl;
        int ks  = k >> 5;
        int kk  = k & 31;
        int rh  = kk >> 4;
        int tg  = (kk >> 2) & 3;
        int mt  = m >> 4;
        int m15 = m & 15;
        int g   = m15 & 7;
        int rl  = m15 >> 3;
        int l   = g * 4 + tg;
        int r   = rl + 2 * rh;
        g_zfrag[(((blk * 8 + ks) * 8 + mt) * 32 + l) * 4 + r] = pk;
    }
}

// ===================== prep e: e4m3(-2e), row-major [n][k] =====================
__global__ void vq_prep_e_kernel(const float* __restrict__ cb) {
    int id = blockIdx.x * blockDim.x + threadIdx.x;   // pair index
    float a = -2.0f * cb[2 * id];
    float b = -2.0f * cb[2 * id + 1];
    g_ef8[id] = f2_to_e4m3x2(b, a);
}

// ===================== codebook row norms (exact fp32) =====================
__global__ void vq_cbnorm_kernel(const float* __restrict__ cb) {
    int warp = (blockIdx.x * blockDim.x + threadIdx.x) >> 5;
    int lane = threadIdx.x & 31;
    if (warp >= NK) return;
    const float* row = cb + (size_t)warp * NC;
    float s = 0.f;
#pragma unroll
    for (int i = 0; i < NC / 32; i++) {
        float v = row[lane + i * 32];
        s += v * v;
    }
#pragma unroll
    for (int off = 16; off; off >>= 1) s += __shfl_down_sync(0xffffffffu, s, off);
    if (lane == 0) g_cbnorm[warp] = s;
}

// ===================== main kernel: fp8 mma.sync distance + candidate capture ==========
// SMEM layout (bytes):
//   [0, 32768)        A frags (u32[8][8][32][4])
//   [32768, 40960)    B double buffer: 2 x 128 rows x 32B
//   [40960, 73728)    cbnorm (8192 f32)
//   [73728, 75776)    snc[8][64]
//   [75776, 108544)   scand[8][64][16]
#define SM_A     0
#define SM_B     32768
#define SM_BSTG  4096
#define SM_CBN   40960
#define SM_SNC   73728
#define SM_SCAND 75776
#define SM_TOTAL 108544

__global__ void __launch_bounds__(256, 2) vq_argmin_mma_kernel() {
    extern __shared__ char smem[];
    uint32_t sb = smem_u32(smem);
    const int tid  = threadIdx.x;
    const int wid  = tid >> 5;
    const int lane = tid & 31;
    const int wm   = wid >> 2;       // 0..1
    const int wn   = wid & 3;        // 0..3
    const int g    = lane >> 2;      // 0..7
    const int tg   = lane & 3;       // 0..3
    const int blk  = blockIdx.x;
    const int n_base = blk * 128;

    uint4*  Asm   = (uint4*)(smem + SM_A);
    float*  cbn   = (float*)(smem + SM_CBN);
    int*    snc   = (int*)(smem + SM_SNC);          // [8][64]
    int*    scand = (int*)(smem + SM_SCAND);        // [8][64][16]

    // ---- stage A frags + cbnorm, zero counters ----
    {
        const uint4* src = (const uint4*)(g_zfrag + (size_t)blk * 8192);
#pragma unroll
        for (int i = 0; i < 8; i++) Asm[tid + i * 256] = src[tid + i * 256];
        const float4* cs = (const float4*)g_cbnorm;
        float4* cd = (float4*)cbn;
#pragma unroll
        for (int i = 0; i < 8; i++) cd[tid + i * 256] = cs[tid + i * 256];
        snc[tid] = 0;
        snc[tid + 256] = 0;
    }
    __syncthreads();

    // ---- cp.async B loader: 256 threads x 16B = 4KB chunk (128 rows x 32 fp8) ----
    const int brow = tid >> 1;        // 0..127
    const int bhalf = tid & 1;        // 16B half
    {
        const char* src = (const char*)(g_ef8) + (size_t)brow * 256 + bhalf * 16;
        uint32_t dst = sb + SM_B + brow * 32 + bhalf * 16;
        asm volatile("cp.async.cg.shared.global [%0], [%1], 16;" :: "r"(dst), "l"(src));
        asm volatile("cp.async.commit_group;" ::: "memory");
    }

    float acc[4][4][4];
    float minv[8];
#pragma unroll
    for (int i = 0; i < 8; i++) minv[i] = 3.4e38f;

    // B fragment read offsets: lane (g,tg): row = wn*32 + j*8 + g, k-byte = 4*tg (+16)
    uint32_t bOff[4];
#pragma unroll
    for (int j = 0; j < 4; j++)
        bOff[j] = (uint32_t)((wn * 32 + j * 8 + g) * 32 + 4 * tg);

    for (int T = 0; T < 512; T++) {
        const int tile = T >> 3;
        const int ks   = T & 7;

        asm volatile("cp.async.wait_group 0;" ::: "memory");
        __syncthreads();

        if (T + 1 < 512) {
            const int Tn = T + 1;
            const char* src = (const char*)(g_ef8) +
                (size_t)((Tn >> 3) * 128 + brow) * 256 + (Tn & 7) * 32 + bhalf * 16;
            uint32_t dst = sb + SM_B + ((Tn & 1) * SM_BSTG) + brow * 32 + bhalf * 16;
            asm volatile("cp.async.cg.shared.global [%0], [%1], 16;" :: "r"(dst), "l"(src));
            asm volatile("cp.async.commit_group;" ::: "memory");
        }

        if (ks == 0) {
#pragma unroll
            for (int m = 0; m < 4; m++)
#pragma unroll
                for (int j = 0; j < 4; j++)
#pragma unroll
                    for (int r = 0; r < 4; r++) acc[m][j][r] = 0.f;
        }

        const uint32_t bbase = sb + SM_B + (T & 1) * SM_BSTG;
        uint32_t a[4][4];
#pragma unroll
        for (int m2 = 0; m2 < 4; m2++) {
            uint4 v = Asm[(ks * 8 + (wm * 4 + m2)) * 32 + lane];
            a[m2][0] = v.x; a[m2][1] = v.y; a[m2][2] = v.z; a[m2][3] = v.w;
        }
        uint32_t b[4][2];
#pragma unroll
        for (int j = 0; j < 4; j++) {
            asm volatile("ld.shared.b32 %0, [%1];" : "=r"(b[j][0]) : "r"(bbase + bOff[j]));
            asm volatile("ld.shared.b32 %0, [%1];" : "=r"(b[j][1]) : "r"(bbase + bOff[j] + 16));
        }
#pragma unroll
        for (int m2 = 0; m2 < 4; m2++)
#pragma unroll
            for (int j = 0; j < 4; j++) {
                asm volatile(
                    "mma.sync.aligned.m16n8k32.row.col.f32.e4m3.e4m3.f32 "
                    "{%0,%1,%2,%3}, {%4,%5,%6,%7}, {%8,%9}, {%0,%1,%2,%3};"
                    : "+f"(acc[m2][j][0]), "+f"(acc[m2][j][1]),
                      "+f"(acc[m2][j][2]), "+f"(acc[m2][j][3])
                    : "r"(a[m2][0]), "r"(a[m2][1]), "r"(a[m2][2]), "r"(a[m2][3]),
                      "r"(b[j][0]), "r"(b[j][1]));
            }

        if (ks == 7) {
            // -------- per-tile epilogue --------
            const int nb = tile * 128 + wn * 32;
            float2 cb2[4];
#pragma unroll
            for (int j = 0; j < 4; j++)
                cb2[j] = *(const float2*)(cbn + nb + j * 8 + 2 * tg);
#pragma unroll
            for (int mh = 0; mh < 8; mh++) {
                const int m = mh >> 1, h = mh & 1;
                float d0[8];
#pragma unroll
                for (int j = 0; j < 4; j++) {
                    d0[2 * j]     = acc[m][j][2 * h]     + cb2[j].x;
                    d0[2 * j + 1] = acc[m][j][2 * h + 1] + cb2[j].y;
                }
                float lm = d0[0];
#pragma unroll
                for (int i = 1; i < 8; i++) lm = fminf(lm, d0[i]);
                lm = fminf(lm, __shfl_xor_sync(0xffffffffu, lm, 1));
                lm = fminf(lm, __shfl_xor_sync(0xffffffffu, lm, 2));
                if (lm < minv[mh] + DELTA) {
                    const float thr2 = fminf(minv[mh], lm) + DELTA;
                    const int tl = m * 16 + h * 8 + g;
#pragma unroll
                    for (int j = 0; j < 4; j++)
#pragma unroll
                        for (int p = 0; p < 2; p++) {
                            float d = d0[2 * j + p];
                            if (d < thr2) {
                                int slot = atomicAdd(&snc[wid * 64 + tl], 1);
                                if (slot < CAND_CAP)
                                    scand[(wid * 64 + tl) * CAND_CAP + slot] =
                                        nb + j * 8 + 2 * tg + p;
                            }
                        }
                    minv[mh] = fminf(minv[mh], lm);
                }
            }
        }
    }

    __syncthreads();
    // -------- merge 4 N-warps per token --------
    if (tid < 128) {
        const int wmg = tid >> 6, tl = tid & 63;
        const int tok = n_base + tid;
        int total = 0;
        bool ovf = false;
        for (int w = wmg * 4; w < wmg * 4 + 4; w++) {
            int cnum = snc[w * 64 + tl];
            if (cnum > CAND_CAP) { ovf = true; cnum = CAND_CAP; }
            for (int s = 0; s < cnum; s++)
                g_ck[tok * CK_STRIDE + total + s] = scand[(w * 64 + tl) * CAND_CAP + s];
            total += cnum;
        }
        g_nc[tok] = ovf ? 255 : total;
    }
}

// ===================== exact rescoring =====================
__device__ __forceinline__ float vq_exact_dist(const float* __restrict__ cb,
                                               const float zr[8], int k, int lane) {
    const float* cr = cb + (size_t)k * NC + lane;
    float s = 0.f;
#pragma unroll
    for (int u = 0; u < 8; u++) s += zr[u] * cr[u * 32];
#pragma unroll
    for (int off = 16; off; off >>= 1) s += __shfl_xor_sync(0xffffffffu, s, off);
    return g_cbnorm[k] - 2.0f * s;
}

__global__ void vq_rescore_kernel(const float* __restrict__ z, const float* __restrict__ cb) {
    int n = (blockIdx.x * blockDim.x + threadIdx.x) >> 5;
    int lane = threadIdx.x & 31;
    if (n >= NTOK) return;
    int nc = g_nc[n];

    int b = n >> 10, hw = n & 1023;
    const float* zp = z + (size_t)b * NC * NHW + hw;
    float zr[8];
#pragma unroll
    for (int u = 0; u < 8; u++) zr[u] = zp[(size_t)(lane + u * 32) * NHW];

    float bd = 3.4e38f;
    int bk = 0x7fffffff;
    if (nc < 255) {
        for (int i = 0; i < nc; i++) {
            int k = g_ck[n * CK_STRIDE + i];
            float d = vq_exact_dist(cb, zr, k, lane);
            if (d < bd || (d == bd && k < bk)) { bd = d; bk = k; }
        }
    } else {
        for (int k = 0; k < NK; k++) {
            float d = vq_exact_dist(cb, zr, k, lane);
            if (d < bd || (d == bd && k < bk)) { bd = d; bk = k; }
        }
    }
    if (lane == 0) g_idx[n] = bk;
}

// ===================== writeback: 4 channels per thread, 16B codebook gathers ==========
__global__ void vq_writeback_kernel(const float* __restrict__ z, const float* __restrict__ cb,
                                    float* __restrict__ out) {
    const int tid = threadIdx.x;
    const int gid = blockIdx.x * 256 + tid;      // [b][cq][hw], cq = c/4
    const int hw  = gid & 1023;
    const int cq  = (gid >> 10) & 63;
    const int b   = gid >> 16;
    const int n   = (b << 10) | hw;
    const int c   = cq * 4;

    const int k = g_idx[n];
    float4 q = *(const float4*)(cb + (size_t)k * NC + c);

    const size_t zbase = ((size_t)b * NC + c) * NHW + hw;
    float zv0 = z[zbase];
    float zv1 = z[zbase + NHW];
    float zv2 = z[zbase + 2 * NHW];
    float zv3 = z[zbase + 3 * NHW];

    out[zbase]           = zv0 + (q.x - zv0);
    out[zbase + NHW]     = zv1 + (q.y - zv1);
    out[zbase + 2 * NHW] = zv2 + (q.z - zv2);
    out[zbase + 3 * NHW] = zv3 + (q.w - zv3);

    if (cq == 0) {
        atomicAdd(&g_counts[k], 1);
        out[NQ + n] = (float)k;
    }

    float dx = zv0 - q.x, dy = zv1 - q.y, dz = zv2 - q.z, dw = zv3 - q.w;
    double s = (double)dx * dx + (double)dy * dy + (double)dz * dz + (double)dw * dw;
#pragma unroll
    for (int off = 16; off; off >>= 1) s += __shfl_down_sync(0xffffffffu, s, off);
    __shared__ double ws[8];
    if ((tid & 31) == 0) ws[tid >> 5] = s;
    __syncthreads();
    if (tid == 0) {
        double t = 0.0;
#pragma unroll
        for (int i = 0; i < 8; i++) t += ws[i];
        atomicAdd(&g_loss, t);
    }
}

// ===================== finalize =====================
__global__ void vq_finalize_kernel(float* __restrict__ out) {
    const int tid = threadIdx.x;
    double s = 0.0;
    for (int k = tid; k < NK; k += 256) {
        int c = g_counts[k];
        if (c > 0) {
            double p = (double)c / (double)NTOK;
            s += p * log(p);
        }
    }
#pragma unroll
    for (int off = 16; off; off >>= 1) s += __shfl_down_sync(0xffffffffu, s, off);
    __shared__ double ws[8];
    if ((tid & 31) == 0) ws[tid >> 5] = s;
    __syncthreads();
    if (tid == 0) {
        double t = 0.0;
#pragma unroll
        for (int i = 0; i < 8; i++) t += ws[i];
        float perp = (float)exp(-t);
        float loss = (float)(g_loss / (double)NQ);
        out[NQ + NTOK + 0] = perp;
        out[NQ + NTOK + 1] = loss;
        out[NQ + NTOK + 2] = loss;
    }
}

// ===================== launch =====================
extern "C" void kernel_launch(void* const* d_in, const int* in_sizes, int n_in,
                              void* d_out, int out_size) {
    const float* z  = (const float*)d_in[0];
    const float* cb = (const float*)d_in[1];
    float* out = (float*)d_out;

    static bool attr_set = false;
    if (!attr_set) {
        cudaFuncSetAttribute(vq_argmin_mma_kernel,
                             cudaFuncAttributeMaxDynamicSharedMemorySize, SM_TOTAL);
        attr_set = true;
    }

    vq_init_kernel<<<NK / 256, 256>>>();
    vq_prep_z_kernel<<<dim3(32, 8, 16), 256>>>(z);
    vq_prep_e_kernel<<<(NK * NC / 2) / 256, 256>>>(cb);
    vq_cbnorm_kernel<<<NK / 8, 256>>>(cb);
    vq_argmin_mma_kernel<<<NTOK / 128, 256, SM_TOTAL>>>();
    vq_rescore_kernel<<<NTOK / 8, 256>>>(z, cb);
    vq_writeback_kernel<<<NQ / 1024, 256>>>(z, cb, out);
    vq_finalize_kernel<<<1, 256>>>(out);
}

// round 6
// speedup vs baseline: 17.2956x; 17.2956x over previous
#include <cuda_runtime.h>
#include <cuda_bf16.h>
#include <math.h>
#include <stdint.h>

// ===================== problem constants =====================
#define NB   16
#define NC   256
#define NHW  1024
#define NTOK (NB * NHW)        // 16384
#define NK   8192
#define NQ   (NB * NC * NHW)   // 4194304

#define DELTA 0.75f
#define CAND_CAP 16
#define CK_STRIDE 64

// ===================== device scratch =====================
__device__ __align__(16) uint32_t g_zfrag[(NTOK / 128) * 16384];  // 8MB, frag-order A
__device__ __align__(16) __nv_bfloat16 g_ebf[NK * NC];            // 4MB, bf16(-2e)
__device__ float  g_cbnorm[NK];
__device__ __align__(16) int g_idx[NTOK];
__device__ int    g_nc[NTOK];
__device__ int    g_ck[NTOK * CK_STRIDE];
__device__ int    g_counts[NK];
__device__ double g_loss;

__device__ __forceinline__ uint32_t smem_u32(const void* p) {
    uint32_t a;
    asm("{ .reg .u64 t; cvta.to.shared.u64 t, %1; cvt.u32.u64 %0, t; }" : "=r"(a) : "l"(p));
    return a;
}

// ===================== init =====================
__global__ void vq_init_kernel() {
    int id = blockIdx.x * blockDim.x + threadIdx.x;
    if (id < NK) g_counts[id] = 0;
    if (id == 0) g_loss = 0.0;
}

// ===================== prep z: transpose + bf16 + mma-fragment order =====================
__global__ void vq_prep_z_kernel(const float* __restrict__ z) {
    __shared__ float t[32][33];
    int b   = blockIdx.z;
    int hw0 = blockIdx.x * 32;
    int c0  = blockIdx.y * 32;
    int lane = threadIdx.x & 31;
    int gq   = threadIdx.x >> 5;   // 0..7
    const float* zp = z + ((size_t)b * NC + c0) * NHW + hw0;
#pragma unroll
    for (int r = 0; r < 4; r++) {
        int cc = gq * 4 + r;
        t[cc][lane] = zp[(size_t)cc * NHW + lane];
    }
    __syncthreads();
#pragma unroll
    for (int it = 0; it < 2; it++) {
        int slot = threadIdx.x + it * 256;      // 0..511
        int hw_i = slot & 31;
        int cp   = slot >> 5;                   // 0..15
        int c    = c0 + 2 * cp;
        float v0 = t[2 * cp][hw_i];
        float v1 = t[2 * cp + 1][hw_i];
        uint32_t lo = (uint32_t)__bfloat16_as_ushort(__float2bfloat16(v0));
        uint32_t hi = (uint32_t)__bfloat16_as_ushort(__float2bfloat16(v1));
        uint32_t pk = lo | (hi << 16);

        int n   = b * NHW + hw0 + hw_i;
        int m   = n & 127;
        int blk = n >> 7;
        int ks  = c >> 4;
        int kk  = c & 15;
        int mt  = m >> 4;
        int m15 = m & 15;
        int g   = m15 & 7;
        int rl  = m15 >> 3;
        int tg  = (kk >> 1) & 3;
        int rh  = kk >> 3;
        int l   = g * 4 + tg;
        int r   = rl + 2 * rh;
        g_zfrag[(((blk * 16 + ks) * 8 + mt) * 32 + l) * 4 + r] = pk;
    }
}

// ===================== prep e: bf16(-2e), row-major [n][k] =====================
__global__ void vq_prep_e_kernel(const float* __restrict__ cb) {
    int id = blockIdx.x * blockDim.x + threadIdx.x;
    g_ebf[id] = __float2bfloat16(-2.0f * cb[id]);
}

// ===================== codebook row norms (exact fp32) =====================
__global__ void vq_cbnorm_kernel(const float* __restrict__ cb) {
    int warp = (blockIdx.x * blockDim.x + threadIdx.x) >> 5;
    int lane = threadIdx.x & 31;
    if (warp >= NK) return;
    const float* row = cb + (size_t)warp * NC;
    float s = 0.f;
#pragma unroll
    for (int i = 0; i < NC / 32; i++) {
        float v = row[lane + i * 32];
        s += v * v;
    }
#pragma unroll
    for (int off = 16; off; off >>= 1) s += __shfl_down_sync(0xffffffffu, s, off);
    if (lane == 0) g_cbnorm[warp] = s;
}

// ===================== main kernel: bf16 mma.sync, 512 threads (16 warps) ==========
// warp (wm 0..3, wn 0..3): M rows [wm*32, wm*32+32), N cols [wn*32, wn*32+32)
// SMEM layout (bytes):
//   [0, 65536)        A frags (u32[16][8][32][4])
//   [65536, 86016)    B double buffer: 2 x 128 rows x 80B
//   [86016, 118784)   cbnorm (8192 f32)
//   [118784, 120832)  snc[16][32]
//   [120832, 153600)  scand[16][32][16]
#define SM_A     0
#define SM_B     65536
#define SM_BSTG  10240
#define SM_CBN   86016
#define SM_SNC   118784
#define SM_SCAND 120832
#define SM_TOTAL 153600

__global__ void __launch_bounds__(512, 1) vq_argmin_mma_kernel() {
    extern __shared__ char smem[];
    uint32_t sb = smem_u32(smem);
    const int tid  = threadIdx.x;
    const int wid  = tid >> 5;
    const int lane = tid & 31;
    const int wm   = wid >> 2;       // 0..3
    const int wn   = wid & 3;        // 0..3
    const int g    = lane >> 2;      // 0..7
    const int tg   = lane & 3;       // 0..3
    const int blk  = blockIdx.x;
    const int n_base = blk * 128;

    uint4*  Asm   = (uint4*)(smem + SM_A);
    float*  cbn   = (float*)(smem + SM_CBN);
    int*    snc   = (int*)(smem + SM_SNC);          // [16][32]
    int*    scand = (int*)(smem + SM_SCAND);        // [16][32][16]

    // ---- stage A frags + cbnorm, zero counters ----
    {
        const uint4* src = (const uint4*)(g_zfrag + (size_t)blk * 16384);
#pragma unroll
        for (int i = 0; i < 8; i++) Asm[tid + i * 512] = src[tid + i * 512];
        const float4* cs = (const float4*)g_cbnorm;
        float4* cd = (float4*)cbn;
#pragma unroll
        for (int i = 0; i < 4; i++) cd[tid + i * 512] = cs[tid + i * 512];
        snc[tid] = 0;
    }
    __syncthreads();

    // ---- cp.async B loader: 512 threads x 16B = 8KB chunk (128 rows x 64B) ----
    const int brow = tid >> 2;        // 0..127
    const int bq   = tid & 3;         // 16B quarter
    {
        const char* src = (const char*)(g_ebf) + (size_t)brow * 512 + bq * 16;
        uint32_t dst = sb + SM_B + brow * 80 + bq * 16;
        asm volatile("cp.async.cg.shared.global [%0], [%1], 16;" :: "r"(dst), "l"(src));
        asm volatile("cp.async.commit_group;" ::: "memory");
    }

    float acc[2][4][4];
    float minv[4];
#pragma unroll
    for (int i = 0; i < 4; i++) minv[i] = 3.4e38f;

    // ldmatrix source addresses (fixed within buffer)
    const int rowsel = lane >> 4;             // 0/1
    const int kbsel  = ((lane >> 3) & 1) * 16;
    const uint32_t bA1 = (uint32_t)(((wn * 4 + rowsel) * 8 + (lane & 7)) * 80 + kbsel);
    const uint32_t bA2 = (uint32_t)(((wn * 4 + 2 + rowsel) * 8 + (lane & 7)) * 80 + kbsel);

    for (int T = 0; T < 512; T++) {
        const int tile = T >> 3;
        const int c    = T & 7;

        asm volatile("cp.async.wait_group 0;" ::: "memory");
        __syncthreads();

        if (T + 1 < 512) {
            const int Tn = T + 1;
            const char* src = (const char*)(g_ebf) +
                (size_t)((Tn >> 3) * 128 + brow) * 512 + (Tn & 7) * 64 + bq * 16;
            uint32_t dst = sb + SM_B + ((Tn & 1) * SM_BSTG) + brow * 80 + bq * 16;
            asm volatile("cp.async.cg.shared.global [%0], [%1], 16;" :: "r"(dst), "l"(src));
            asm volatile("cp.async.commit_group;" ::: "memory");
        }

        if (c == 0) {
#pragma unroll
            for (int m = 0; m < 2; m++)
#pragma unroll
                for (int j = 0; j < 4; j++)
#pragma unroll
                    for (int r = 0; r < 4; r++) acc[m][j][r] = 0.f;
        }

        const uint32_t bbase = sb + SM_B + (T & 1) * SM_BSTG;
#pragma unroll
        for (int s2 = 0; s2 < 2; s2++) {
            const int ks = c * 2 + s2;
            uint32_t a[2][4];
#pragma unroll
            for (int m2 = 0; m2 < 2; m2++) {
                uint4 v = Asm[(ks * 8 + (wm * 2 + m2)) * 32 + lane];
                a[m2][0] = v.x; a[m2][1] = v.y; a[m2][2] = v.z; a[m2][3] = v.w;
            }
            uint32_t b[4][2];
            asm volatile("ldmatrix.sync.aligned.m8n8.x4.shared.b16 {%0,%1,%2,%3}, [%4];"
                : "=r"(b[0][0]), "=r"(b[0][1]), "=r"(b[1][0]), "=r"(b[1][1])
                : "r"(bbase + bA1 + s2 * 32));
            asm volatile("ldmatrix.sync.aligned.m8n8.x4.shared.b16 {%0,%1,%2,%3}, [%4];"
                : "=r"(b[2][0]), "=r"(b[2][1]), "=r"(b[3][0]), "=r"(b[3][1])
                : "r"(bbase + bA2 + s2 * 32));
#pragma unroll
            for (int m2 = 0; m2 < 2; m2++)
#pragma unroll
                for (int j = 0; j < 4; j++) {
                    asm volatile(
                        "mma.sync.aligned.m16n8k16.row.col.f32.bf16.bf16.f32 "
                        "{%0,%1,%2,%3}, {%4,%5,%6,%7}, {%8,%9}, {%0,%1,%2,%3};"
                        : "+f"(acc[m2][j][0]), "+f"(acc[m2][j][1]),
                          "+f"(acc[m2][j][2]), "+f"(acc[m2][j][3])
                        : "r"(a[m2][0]), "r"(a[m2][1]), "r"(a[m2][2]), "r"(a[m2][3]),
                          "r"(b[j][0]), "r"(b[j][1]));
                }
        }

        if (c == 7) {
            // -------- per-tile epilogue --------
            const int nb = tile * 128 + wn * 32;
            float2 cb2[4];
#pragma unroll
            for (int j = 0; j < 4; j++)
                cb2[j] = *(const float2*)(cbn + nb + j * 8 + 2 * tg);
#pragma unroll
            for (int mh = 0; mh < 4; mh++) {
                const int m = mh >> 1, h = mh & 1;
                float d0[8];
#pragma unroll
                for (int j = 0; j < 4; j++) {
                    d0[2 * j]     = acc[m][j][2 * h]     + cb2[j].x;
                    d0[2 * j + 1] = acc[m][j][2 * h + 1] + cb2[j].y;
                }
                float lm = d0[0];
#pragma unroll
                for (int i = 1; i < 8; i++) lm = fminf(lm, d0[i]);
                lm = fminf(lm, __shfl_xor_sync(0xffffffffu, lm, 1));
                lm = fminf(lm, __shfl_xor_sync(0xffffffffu, lm, 2));
                if (lm < minv[mh] + DELTA) {
                    const float thr2 = fminf(minv[mh], lm) + DELTA;
                    const int tl = m * 16 + h * 8 + g;     // 0..31 within warp M-quarter
#pragma unroll
                    for (int j = 0; j < 4; j++)
#pragma unroll
                        for (int p = 0; p < 2; p++) {
                            float d = d0[2 * j + p];
                            if (d < thr2) {
                                int slot = atomicAdd(&snc[wid * 32 + tl], 1);
                                if (slot < CAND_CAP)
                                    scand[(wid * 32 + tl) * CAND_CAP + slot] =
                                        nb + j * 8 + 2 * tg + p;
                            }
                        }
                    minv[mh] = fminf(minv[mh], lm);
                }
            }
        }
    }

    __syncthreads();
    // -------- merge 4 N-warps per token --------
    if (tid < 128) {
        const int wmg = tid >> 5, tl = tid & 31;
        const int tok = n_base + tid;
        int total = 0;
        bool ovf = false;
        for (int w = wmg * 4; w < wmg * 4 + 4; w++) {
            int cnum = snc[w * 32 + tl];
            if (cnum > CAND_CAP) { ovf = true; cnum = CAND_CAP; }
            for (int s = 0; s < cnum; s++)
                g_ck[tok * CK_STRIDE + total + s] = scand[(w * 32 + tl) * CAND_CAP + s];
            total += cnum;
        }
        g_nc[tok] = ovf ? 255 : total;
    }
}

// ===================== exact rescoring =====================
__device__ __forceinline__ float vq_exact_dist(const float* __restrict__ cb,
                                               const float zr[8], int k, int lane) {
    const float* cr = cb + (size_t)k * NC + lane;
    float s = 0.f;
#pragma unroll
    for (int u = 0; u < 8; u++) s += zr[u] * cr[u * 32];
#pragma unroll
    for (int off = 16; off; off >>= 1) s += __shfl_xor_sync(0xffffffffu, s, off);
    return g_cbnorm[k] - 2.0f * s;
}

__global__ void vq_rescore_kernel(const float* __restrict__ z, const float* __restrict__ cb) {
    int n = (blockIdx.x * blockDim.x + threadIdx.x) >> 5;
    int lane = threadIdx.x & 31;
    if (n >= NTOK) return;
    int nc = g_nc[n];

    int b = n >> 10, hw = n & 1023;
    const float* zp = z + (size_t)b * NC * NHW + hw;
    float zr[8];
#pragma unroll
    for (int u = 0; u < 8; u++) zr[u] = zp[(size_t)(lane + u * 32) * NHW];

    float bd = 3.4e38f;
    int bk = 0x7fffffff;
    if (nc < 255) {
        for (int i = 0; i < nc; i++) {
            int k = g_ck[n * CK_STRIDE + i];
            float d = vq_exact_dist(cb, zr, k, lane);
            if (d < bd || (d == bd && k < bk)) { bd = d; bk = k; }
        }
    } else {
        for (int k = 0; k < NK; k++) {
            float d = vq_exact_dist(cb, zr, k, lane);
            if (d < bd || (d == bd && k < bk)) { bd = d; bk = k; }
        }
    }
    if (lane == 0) g_idx[n] = bk;
}

// ===================== writeback: 4 channels per thread, 16B codebook gathers ==========
__global__ void vq_writeback_kernel(const float* __restrict__ z, const float* __restrict__ cb,
                                    float* __restrict__ out) {
    const int tid = threadIdx.x;
    const int gid = blockIdx.x * 256 + tid;      // [b][cq][hw], cq = c/4
    const int hw  = gid & 1023;
    const int cq  = (gid >> 10) & 63;
    const int b   = gid >> 16;
    const int n   = (b << 10) | hw;
    const int c   = cq * 4;

    const int k = g_idx[n];
    float4 q = *(const float4*)(cb + (size_t)k * NC + c);

    const size_t zbase = ((size_t)b * NC + c) * NHW + hw;
    float zv0 = z[zbase];
    float zv1 = z[zbase + NHW];
    float zv2 = z[zbase + 2 * NHW];
    float zv3 = z[zbase + 3 * NHW];

    out[zbase]           = zv0 + (q.x - zv0);
    out[zbase + NHW]     = zv1 + (q.y - zv1);
    out[zbase + 2 * NHW] = zv2 + (q.z - zv2);
    out[zbase + 3 * NHW] = zv3 + (q.w - zv3);

    if (cq == 0) {
        atomicAdd(&g_counts[k], 1);
        out[NQ + n] = (float)k;
    }

    float dx = zv0 - q.x, dy = zv1 - q.y, dz = zv2 - q.z, dw = zv3 - q.w;
    double s = (double)dx * dx + (double)dy * dy + (double)dz * dz + (double)dw * dw;
#pragma unroll
    for (int off = 16; off; off >>= 1) s += __shfl_down_sync(0xffffffffu, s, off);
    __shared__ double ws[8];
    if ((tid & 31) == 0) ws[tid >> 5] = s;
    __syncthreads();
    if (tid == 0) {
        double t = 0.0;
#pragma unroll
        for (int i = 0; i < 8; i++) t += ws[i];
        atomicAdd(&g_loss, t);
    }
}

// ===================== finalize =====================
__global__ void vq_finalize_kernel(float* __restrict__ out) {
    const int tid = threadIdx.x;
    double s = 0.0;
    for (int k = tid; k < NK; k += 256) {
        int c = g_counts[k];
        if (c > 0) {
            double p = (double)c / (double)NTOK;
            s += p * log(p);
        }
    }
#pragma unroll
    for (int off = 16; off; off >>= 1) s += __shfl_down_sync(0xffffffffu, s, off);
    __shared__ double ws[8];
    if ((tid & 31) == 0) ws[tid >> 5] = s;
    __syncthreads();
    if (tid == 0) {
        double t = 0.0;
#pragma unroll
        for (int i = 0; i < 8; i++) t += ws[i];
        float perp = (float)exp(-t);
        float loss = (float)(g_loss / (double)NQ);
        out[NQ + NTOK + 0] = perp;
        out[NQ + NTOK + 1] = loss;
        out[NQ + NTOK + 2] = loss;
    }
}

// ===================== launch =====================
extern "C" void kernel_launch(void* const* d_in, const int* in_sizes, int n_in,
                              void* d_out, int out_size) {
    const float* z  = (const float*)d_in[0];
    const float* cb = (const float*)d_in[1];
    float* out = (float*)d_out;

    static bool attr_set = false;
    if (!attr_set) {
        cudaFuncSetAttribute(vq_argmin_mma_kernel,
                             cudaFuncAttributeMaxDynamicSharedMemorySize, SM_TOTAL);
        attr_set = true;
    }

    vq_init_kernel<<<NK / 256, 256>>>();
    vq_prep_z_kernel<<<dim3(32, 8, 16), 256>>>(z);
    vq_prep_e_kernel<<<(NK * NC) / 256, 256>>>(cb);
    vq_cbnorm_kernel<<<NK / 8, 256>>>(cb);
    vq_argmin_mma_kernel<<<NTOK / 128, 512, SM_TOTAL>>>();
    vq_rescore_kernel<<<NTOK / 8, 256>>>(z, cb);
    vq_writeback_kernel<<<NQ / 1024, 256>>>(z, cb, out);
    vq_finalize_kernel<<<1, 256>>>(out);
}

// round 7
// speedup vs baseline: 18.0786x; 1.0453x over previous
#include <cuda_runtime.h>
#include <cuda_bf16.h>
#include <math.h>
#include <stdint.h>

// ===================== problem constants =====================
#define NB   16
#define NC   256
#define NHW  1024
#define NTOK (NB * NHW)        // 16384
#define NK   8192
#define NQ   (NB * NC * NHW)   // 4194304

#define DELTA 0.75f
#define CAND_CAP 16
#define CK_STRIDE 64

// ===================== device scratch =====================
__device__ __align__(16) uint32_t g_zfrag[(NTOK / 128) * 16384];  // 8MB, frag-order A
__device__ __align__(16) __nv_bfloat16 g_ebf[NK * NC];            // 4MB, bf16(-2e)
__device__ __align__(16) float g_zt[NTOK * NC];                   // 16MB, z transposed [n][c]
__device__ float  g_cbnorm[NK];
__device__ __align__(16) int g_idx[NTOK];
__device__ int    g_nc[NTOK];
__device__ int    g_ck[NTOK * CK_STRIDE];
__device__ int    g_counts[NK];
__device__ double g_loss;

__device__ __forceinline__ uint32_t smem_u32(const void* p) {
    uint32_t a;
    asm("{ .reg .u64 t; cvta.to.shared.u64 t, %1; cvt.u32.u64 %0, t; }" : "=r"(a) : "l"(p));
    return a;
}

// ===================== prep z: transpose + bf16 frag order + fp32 transposed copy ======
__global__ void vq_prep_z_kernel(const float* __restrict__ z) {
    __shared__ float t[32][33];
    int b   = blockIdx.z;
    int hw0 = blockIdx.x * 32;
    int c0  = blockIdx.y * 32;
    int lane = threadIdx.x & 31;
    int gq   = threadIdx.x >> 5;   // 0..7
    const float* zp = z + ((size_t)b * NC + c0) * NHW + hw0;
#pragma unroll
    for (int r = 0; r < 4; r++) {
        int cc = gq * 4 + r;
        t[cc][lane] = zp[(size_t)cc * NHW + lane];
    }
    __syncthreads();
#pragma unroll
    for (int it = 0; it < 2; it++) {
        int slot = threadIdx.x + it * 256;      // 0..511
        int hw_i = slot & 31;
        int cp   = slot >> 5;                   // 0..15
        int c    = c0 + 2 * cp;
        float v0 = t[2 * cp][hw_i];
        float v1 = t[2 * cp + 1][hw_i];
        uint32_t lo = (uint32_t)__bfloat16_as_ushort(__float2bfloat16(v0));
        uint32_t hi = (uint32_t)__bfloat16_as_ushort(__float2bfloat16(v1));
        uint32_t pk = lo | (hi << 16);

        int n   = b * NHW + hw0 + hw_i;
        int m   = n & 127;
        int blk = n >> 7;
        int ks  = c >> 4;
        int kk  = c & 15;
        int mt  = m >> 4;
        int m15 = m & 15;
        int g   = m15 & 7;
        int rl  = m15 >> 3;
        int tg  = (kk >> 1) & 3;
        int rh  = kk >> 3;
        int l   = g * 4 + tg;
        int r   = rl + 2 * rh;
        g_zfrag[(((blk * 16 + ks) * 8 + mt) * 32 + l) * 4 + r] = pk;
    }
    // coalesced transposed fp32 copy: warp gq covers 4 tokens, lane = channel
#pragma unroll
    for (int i = 0; i < 4; i++) {
        int tok_l = gq * 4 + i;
        int n = b * NHW + hw0 + tok_l;
        g_zt[(size_t)n * NC + c0 + lane] = t[lane][tok_l];
    }
}

// ===================== prep e (+ init counts/loss): bf16(-2e) row-major =================
__global__ void vq_prep_e_kernel(const float* __restrict__ cb) {
    int id = blockIdx.x * blockDim.x + threadIdx.x;
    g_ebf[id] = __float2bfloat16(-2.0f * cb[id]);
    if (id < NK) g_counts[id] = 0;
    if (id == 0) g_loss = 0.0;
}

// ===================== codebook row norms (exact fp32) =====================
__global__ void vq_cbnorm_kernel(const float* __restrict__ cb) {
    int warp = (blockIdx.x * blockDim.x + threadIdx.x) >> 5;
    int lane = threadIdx.x & 31;
    if (warp >= NK) return;
    const float* row = cb + (size_t)warp * NC;
    float s = 0.f;
#pragma unroll
    for (int i = 0; i < NC / 32; i++) {
        float v = row[lane + i * 32];
        s += v * v;
    }
#pragma unroll
    for (int off = 16; off; off >>= 1) s += __shfl_down_sync(0xffffffffu, s, off);
    if (lane == 0) g_cbnorm[warp] = s;
}

// ===================== main kernel: bf16 mma.sync, 512 threads, 128B B-chunks ==========
// warp (wm 0..3, wn 0..3): M rows [wm*32,+32), N cols [wn*32,+32)
// SMEM layout (bytes):
//   [0, 65536)         A frags (u32[16][8][32][4])
//   [65536, 102400)    B double buffer: 2 x 128 rows x 144B (128B data + 16 pad)
//   [102400, 135168)   cbnorm (8192 f32)
//   [135168, 137216)   snc[16][32]
//   [137216, 169984)   scand[16][32][16]
#define SM_A     0
#define SM_B     65536
#define SM_BSTG  18432
#define BROW_STRIDE 144
#define SM_CBN   102400
#define SM_SNC   135168
#define SM_SCAND 137216
#define SM_TOTAL 169984

__global__ void __launch_bounds__(512, 1) vq_argmin_mma_kernel() {
    extern __shared__ char smem[];
    uint32_t sb = smem_u32(smem);
    const int tid  = threadIdx.x;
    const int wid  = tid >> 5;
    const int lane = tid & 31;
    const int wm   = wid >> 2;       // 0..3
    const int wn   = wid & 3;        // 0..3
    const int g    = lane >> 2;      // 0..7
    const int tg   = lane & 3;       // 0..3
    const int blk  = blockIdx.x;
    const int n_base = blk * 128;

    uint4*  Asm   = (uint4*)(smem + SM_A);
    float*  cbn   = (float*)(smem + SM_CBN);
    int*    snc   = (int*)(smem + SM_SNC);          // [16][32]
    int*    scand = (int*)(smem + SM_SCAND);        // [16][32][16]

    // ---- stage A frags + cbnorm, zero counters ----
    {
        const uint4* src = (const uint4*)(g_zfrag + (size_t)blk * 16384);
#pragma unroll
        for (int i = 0; i < 8; i++) Asm[tid + i * 512] = src[tid + i * 512];
        const float4* cs = (const float4*)g_cbnorm;
        float4* cd = (float4*)cbn;
#pragma unroll
        for (int i = 0; i < 4; i++) cd[tid + i * 512] = cs[tid + i * 512];
        snc[tid] = 0;
    }
    __syncthreads();

    // ---- cp.async B loader: per chunk 128 rows x 128B; thread -> (row, 32B quarter) ----
    const int brow = tid >> 2;        // 0..127
    const int bq   = tid & 3;         // 32B quarter
    {
        // chunk T=0: tile 0, quarter 0
        const char* src = (const char*)(g_ebf) + (size_t)brow * 512 + bq * 32;
        uint32_t dst = sb + SM_B + brow * BROW_STRIDE + bq * 32;
        asm volatile("cp.async.cg.shared.global [%0], [%1], 16;" :: "r"(dst), "l"(src));
        asm volatile("cp.async.cg.shared.global [%0], [%1], 16;" :: "r"(dst + 16), "l"(src + 16));
        asm volatile("cp.async.commit_group;" ::: "memory");
    }

    float acc[2][4][4];
    float minv[4];
#pragma unroll
    for (int i = 0; i < 4; i++) minv[i] = 3.4e38f;

    // ldmatrix source addresses (fixed within buffer); row stride 144B
    const int rowsel = lane >> 4;             // 0/1
    const int kbsel  = ((lane >> 3) & 1) * 16;
    const uint32_t bA1 = (uint32_t)(((wn * 4 + rowsel) * 8 + (lane & 7)) * BROW_STRIDE + kbsel);
    const uint32_t bA2 = (uint32_t)(((wn * 4 + 2 + rowsel) * 8 + (lane & 7)) * BROW_STRIDE + kbsel);

    for (int T = 0; T < 256; T++) {
        const int tile = T >> 2;
        const int q2   = T & 3;            // 128B quarter of the 512B codebook row

        asm volatile("cp.async.wait_group 0;" ::: "memory");
        __syncthreads();

        if (T + 1 < 256) {
            const int Tn = T + 1;
            const char* src = (const char*)(g_ebf) +
                (size_t)((Tn >> 2) * 128 + brow) * 512 + (Tn & 3) * 128 + bq * 32;
            uint32_t dst = sb + SM_B + ((Tn & 1) * SM_BSTG) + brow * BROW_STRIDE + bq * 32;
            asm volatile("cp.async.cg.shared.global [%0], [%1], 16;" :: "r"(dst), "l"(src));
            asm volatile("cp.async.cg.shared.global [%0], [%1], 16;" :: "r"(dst + 16), "l"(src + 16));
            asm volatile("cp.async.commit_group;" ::: "memory");
        }

        if (q2 == 0) {
#pragma unroll
            for (int m = 0; m < 2; m++)
#pragma unroll
                for (int j = 0; j < 4; j++)
#pragma unroll
                    for (int r = 0; r < 4; r++) acc[m][j][r] = 0.f;
        }

        const uint32_t bbase = sb + SM_B + (T & 1) * SM_BSTG;
#pragma unroll
        for (int s2 = 0; s2 < 4; s2++) {
            const int ks = q2 * 4 + s2;
            uint32_t a[2][4];
#pragma unroll
            for (int m2 = 0; m2 < 2; m2++) {
                uint4 v = Asm[(ks * 8 + (wm * 2 + m2)) * 32 + lane];
                a[m2][0] = v.x; a[m2][1] = v.y; a[m2][2] = v.z; a[m2][3] = v.w;
            }
            uint32_t b[4][2];
            asm volatile("ldmatrix.sync.aligned.m8n8.x4.shared.b16 {%0,%1,%2,%3}, [%4];"
                : "=r"(b[0][0]), "=r"(b[0][1]), "=r"(b[1][0]), "=r"(b[1][1])
                : "r"(bbase + bA1 + s2 * 32));
            asm volatile("ldmatrix.sync.aligned.m8n8.x4.shared.b16 {%0,%1,%2,%3}, [%4];"
                : "=r"(b[2][0]), "=r"(b[2][1]), "=r"(b[3][0]), "=r"(b[3][1])
                : "r"(bbase + bA2 + s2 * 32));
#pragma unroll
            for (int m2 = 0; m2 < 2; m2++)
#pragma unroll
                for (int j = 0; j < 4; j++) {
                    asm volatile(
                        "mma.sync.aligned.m16n8k16.row.col.f32.bf16.bf16.f32 "
                        "{%0,%1,%2,%3}, {%4,%5,%6,%7}, {%8,%9}, {%0,%1,%2,%3};"
                        : "+f"(acc[m2][j][0]), "+f"(acc[m2][j][1]),
                          "+f"(acc[m2][j][2]), "+f"(acc[m2][j][3])
                        : "r"(a[m2][0]), "r"(a[m2][1]), "r"(a[m2][2]), "r"(a[m2][3]),
                          "r"(b[j][0]), "r"(b[j][1]));
                }
        }

        if (q2 == 3) {
            // -------- per-tile epilogue --------
            const int nb = tile * 128 + wn * 32;
            float2 cb2[4];
#pragma unroll
            for (int j = 0; j < 4; j++)
                cb2[j] = *(const float2*)(cbn + nb + j * 8 + 2 * tg);
#pragma unroll
            for (int mh = 0; mh < 4; mh++) {
                const int m = mh >> 1, h = mh & 1;
                float d0[8];
#pragma unroll
                for (int j = 0; j < 4; j++) {
                    d0[2 * j]     = acc[m][j][2 * h]     + cb2[j].x;
                    d0[2 * j + 1] = acc[m][j][2 * h + 1] + cb2[j].y;
                }
                float lm = d0[0];
#pragma unroll
                for (int i = 1; i < 8; i++) lm = fminf(lm, d0[i]);
                lm = fminf(lm, __shfl_xor_sync(0xffffffffu, lm, 1));
                lm = fminf(lm, __shfl_xor_sync(0xffffffffu, lm, 2));
                if (lm < minv[mh] + DELTA) {
                    const float thr2 = fminf(minv[mh], lm) + DELTA;
                    const int tl = m * 16 + h * 8 + g;
#pragma unroll
                    for (int j = 0; j < 4; j++)
#pragma unroll
                        for (int p = 0; p < 2; p++) {
                            float d = d0[2 * j + p];
                            if (d < thr2) {
                                int slot = atomicAdd(&snc[wid * 32 + tl], 1);
                                if (slot < CAND_CAP)
                                    scand[(wid * 32 + tl) * CAND_CAP + slot] =
                                        nb + j * 8 + 2 * tg + p;
                            }
                        }
                    minv[mh] = fminf(minv[mh], lm);
                }
            }
        }
    }

    __syncthreads();
    // -------- merge 4 N-warps per token --------
    if (tid < 128) {
        const int wmg = tid >> 5, tl = tid & 31;
        const int tok = n_base + tid;
        int total = 0;
        bool ovf = false;
        for (int w = wmg * 4; w < wmg * 4 + 4; w++) {
            int cnum = snc[w * 32 + tl];
            if (cnum > CAND_CAP) { ovf = true; cnum = CAND_CAP; }
            for (int s = 0; s < cnum; s++)
                g_ck[tok * CK_STRIDE + total + s] = scand[(w * 32 + tl) * CAND_CAP + s];
            total += cnum;
        }
        g_nc[tok] = ovf ? 255 : total;
    }
}

// ===================== exact rescoring (coalesced z via g_zt) =====================
__device__ __forceinline__ float vq_exact_dist(const float* __restrict__ cb,
                                               const float zr[8], int k, int lane) {
    const float* cr = cb + (size_t)k * NC + lane;
    float s = 0.f;
#pragma unroll
    for (int u = 0; u < 8; u++) s += zr[u] * cr[u * 32];
#pragma unroll
    for (int off = 16; off; off >>= 1) s += __shfl_xor_sync(0xffffffffu, s, off);
    return g_cbnorm[k] - 2.0f * s;
}

__global__ void vq_rescore_kernel(const float* __restrict__ cb) {
    int n = (blockIdx.x * blockDim.x + threadIdx.x) >> 5;
    int lane = threadIdx.x & 31;
    if (n >= NTOK) return;
    int nc = g_nc[n];

    const float* zp = g_zt + (size_t)n * NC;
    float zr[8];
#pragma unroll
    for (int u = 0; u < 8; u++) zr[u] = zp[lane + u * 32];

    float bd = 3.4e38f;
    int bk = 0x7fffffff;
    if (nc < 255) {
        for (int i = 0; i < nc; i++) {
            int k = g_ck[n * CK_STRIDE + i];
            float d = vq_exact_dist(cb, zr, k, lane);
            if (d < bd || (d == bd && k < bk)) { bd = d; bk = k; }
        }
    } else {
        for (int k = 0; k < NK; k++) {
            float d = vq_exact_dist(cb, zr, k, lane);
            if (d < bd || (d == bd && k < bk)) { bd = d; bk = k; }
        }
    }
    if (lane == 0) g_idx[n] = bk;
}

// ===================== writeback: 4 channels per thread, 16B codebook gathers ==========
__global__ void vq_writeback_kernel(const float* __restrict__ z, const float* __restrict__ cb,
                                    float* __restrict__ out) {
    const int tid = threadIdx.x;
    const int gid = blockIdx.x * 256 + tid;      // [b][cq][hw], cq = c/4
    const int hw  = gid & 1023;
    const int cq  = (gid >> 10) & 63;
    const int b   = gid >> 16;
    const int n   = (b << 10) | hw;
    const int c   = cq * 4;

    const int k = g_idx[n];
    float4 q = *(const float4*)(cb + (size_t)k * NC + c);

    const size_t zbase = ((size_t)b * NC + c) * NHW + hw;
    float zv0 = z[zbase];
    float zv1 = z[zbase + NHW];
    float zv2 = z[zbase + 2 * NHW];
    float zv3 = z[zbase + 3 * NHW];

    out[zbase]           = zv0 + (q.x - zv0);
    out[zbase + NHW]     = zv1 + (q.y - zv1);
    out[zbase + 2 * NHW] = zv2 + (q.z - zv2);
    out[zbase + 3 * NHW] = zv3 + (q.w - zv3);

    if (cq == 0) {
        atomicAdd(&g_counts[k], 1);
        out[NQ + n] = (float)k;
    }

    float dx = zv0 - q.x, dy = zv1 - q.y, dz = zv2 - q.z, dw = zv3 - q.w;
    double s = (double)dx * dx + (double)dy * dy + (double)dz * dz + (double)dw * dw;
#pragma unroll
    for (int off = 16; off; off >>= 1) s += __shfl_down_sync(0xffffffffu, s, off);
    __shared__ double ws[8];
    if ((tid & 31) == 0) ws[tid >> 5] = s;
    __syncthreads();
    if (tid == 0) {
        double t = 0.0;
#pragma unroll
        for (int i = 0; i < 8; i++) t += ws[i];
        atomicAdd(&g_loss, t);
    }
}

// ===================== finalize =====================
__global__ void vq_finalize_kernel(float* __restrict__ out) {
    const int tid = threadIdx.x;
    double s = 0.0;
    for (int k = tid; k < NK; k += 256) {
        int c = g_counts[k];
        if (c > 0) {
            double p = (double)c / (double)NTOK;
            s += p * log(p);
        }
    }
#pragma unroll
    for (int off = 16; off; off >>= 1) s += __shfl_down_sync(0xffffffffu, s, off);
    __shared__ double ws[8];
    if ((tid & 31) == 0) ws[tid >> 5] = s;
    __syncthreads();
    if (tid == 0) {
        double t = 0.0;
#pragma unroll
        for (int i = 0; i < 8; i++) t += ws[i];
        float perp = (float)exp(-t);
        float loss = (float)(g_loss / (double)NQ);
        out[NQ + NTOK + 0] = perp;
        out[NQ + NTOK + 1] = loss;
        out[NQ + NTOK + 2] = loss;
    }
}

// ===================== launch =====================
extern "C" void kernel_launch(void* const* d_in, const int* in_sizes, int n_in,
                              void* d_out, int out_size) {
    const float* z  = (const float*)d_in[0];
    const float* cb = (const float*)d_in[1];
    float* out = (float*)d_out;

    static bool attr_set = false;
    if (!attr_set) {
        cudaFuncSetAttribute(vq_argmin_mma_kernel,
                             cudaFuncAttributeMaxDynamicSharedMemorySize, SM_TOTAL);
        attr_set = true;
    }

    vq_prep_z_kernel<<<dim3(32, 8, 16), 256>>>(z);
    vq_prep_e_kernel<<<(NK * NC) / 256, 256>>>(cb);
    vq_cbnorm_kernel<<<NK / 8, 256>>>(cb);
    vq_argmin_mma_kernel<<<NTOK / 128, 512, SM_TOTAL>>>();
    vq_rescore_kernel<<<NTOK / 8, 256>>>(cb);
    vq_writeback_kernel<<<NQ / 1024, 256>>>(z, cb, out);
    vq_finalize_kernel<<<1, 256>>>(out);
}